// round 1
// baseline (speedup 1.0000x reference)
#include <cuda_runtime.h>

// Problem constants (fixed by reference setup_inputs)
#define BSEQ 512
#define LSEQ 512
#define AA   20
#define CCH  8
#define NREST 8

// Scratch: effective linear map of the conv pipeline, and the column-V matrix.
__device__ float g_Weff[CCH][LSEQ];   // W_eff[c][p]: d out[c] / d h0[p]
__device__ float g_V[AA][AA];         // V[a][i]: column contribution for residue a into channel i

// ---------------------------------------------------------------------------
// Kernel 1: precompute W_eff (blocks 0..7, one output channel each, via the
// adjoint of the conv+pool pipeline) and V (block 8).
// ---------------------------------------------------------------------------
__global__ void precompute_kernel(const float* __restrict__ lpm,
                                  const float* __restrict__ pm,
                                  const float* __restrict__ w_first,
                                  const float* __restrict__ w_rest) {
    const int blk = blockIdx.x;
    const int tid = threadIdx.x;

    if (blk < CCH) {
        __shared__ float bufA[CCH][LSEQ];
        __shared__ float bufB[CCH][LSEQ];
        __shared__ float wsh[CCH * CCH * 3];

        float (*cur)[LSEQ] = bufA;
        float (*nxt)[LSEQ] = bufB;

        // zero + seed: gradient of out[blk] at final length-1, 8-channel tensor
        for (int idx = tid; idx < CCH * LSEQ; idx += blockDim.x)
            (&cur[0][0])[idx] = 0.f;
        __syncthreads();
        if (tid < CCH) cur[tid][0] = (tid == blk) ? 1.f : 0.f;
        __syncthreads();

        int len = 1;
        for (int li = NREST - 1; li >= 0; --li) {
            const int len2 = len * 2;
            // stage layer weights in shared
            for (int idx = tid; idx < CCH * CCH * 3; idx += blockDim.x)
                wsh[idx] = w_rest[li * CCH * CCH * 3 + idx];
            __syncthreads();
            // fused pool-adjoint (0.5 * cur[o][q>>1]) + conv-adjoint
            for (int idx = tid; idx < CCH * len2; idx += blockDim.x) {
                const int i = idx / len2;
                const int p = idx % len2;
                float acc = 0.f;
                #pragma unroll
                for (int o = 0; o < CCH; ++o) {
                    #pragma unroll
                    for (int k = 0; k < 3; ++k) {
                        const int q = p - k + 1;
                        if (q >= 0 && q < len2)
                            acc += wsh[(o * CCH + i) * 3 + k] * 0.5f * cur[o][q >> 1];
                    }
                }
                nxt[i][p] = acc;
            }
            __syncthreads();
            float (*t)[LSEQ] = cur; cur = nxt; nxt = t;
            len = len2;
        }
        // len == 256 here. Fuse first pool-adjoint (256->512) + conv1-adjoint.
        for (int p = tid; p < LSEQ; p += blockDim.x) {
            float acc = 0.f;
            #pragma unroll
            for (int o = 0; o < CCH; ++o) {
                #pragma unroll
                for (int k = 0; k < 3; ++k) {
                    const int q = p - k + 1;
                    if (q >= 0 && q < LSEQ)
                        acc += w_first[o * 3 + k] * 0.5f * cur[o][q >> 1];
                }
            }
            g_Weff[blk][p] = acc;
        }
    } else {
        // V[a][i]: prod = clip(lpm,1e-3,1)*pm (elementwise).
        // k>i -> prod[i][k]; k<i -> prod[k][i]; diag and column 19 are zero.
        for (int idx = tid; idx < AA * AA; idx += blockDim.x) {
            const int a = idx / AA, i = idx % AA;
            float v = 0.f;
            if (i != a && i != AA - 1) {
                const int r = (a < i) ? a : i;
                const int c = (a < i) ? i : a;
                float l = lpm[r * AA + c];
                l = fminf(fmaxf(l, 1e-3f), 1.f);
                v = l * pm[r * AA + c];
            }
            g_V[a][i] = v;
        }
    }
}

// ---------------------------------------------------------------------------
// Kernel 2: one block per sequence b. Scan 512 positions, find the one-hot
// residue, accumulate g[a][c] += W_eff[c][p]; then out = g + V^T-contraction.
// ---------------------------------------------------------------------------
__global__ void __launch_bounds__(LSEQ)
main_kernel(const float* __restrict__ x, float* __restrict__ out) {
    __shared__ float g[AA][CCH];
    const int b = blockIdx.x;
    const int tid = threadIdx.x;   // == position p

    if (tid < AA * CCH) (&g[0][0])[tid] = 0.f;
    __syncthreads();

    // Each thread reads 20 contiguous floats (5x float4, 16B-aligned: 80B stride)
    const float4* xp = reinterpret_cast<const float4*>(
        x + ((size_t)b * LSEQ + tid) * AA);
    int aa = -1;
    #pragma unroll
    for (int v = 0; v < 5; ++v) {
        const float4 f = xp[v];
        if (f.x != 0.f) aa = v * 4 + 0;
        if (f.y != 0.f) aa = v * 4 + 1;
        if (f.z != 0.f) aa = v * 4 + 2;
        if (f.w != 0.f) aa = v * 4 + 3;
    }
    if (aa >= 0) {
        #pragma unroll
        for (int c = 0; c < CCH; ++c)
            atomicAdd(&g[aa][c], g_Weff[c][tid]);
    }
    __syncthreads();

    if (tid < AA * CCH) {
        const int i = tid / CCH;
        const int c = tid % CCH;
        float acc = g[i][c];               // the one-hot (identity) term
        #pragma unroll
        for (int a = 0; a < AA; ++a)
            acc += g_V[a][i] * g[a][c];    // the column-V term
        out[((size_t)b * AA + i) * CCH + c] = acc;
    }
}

// ---------------------------------------------------------------------------
extern "C" void kernel_launch(void* const* d_in, const int* in_sizes, int n_in,
                              void* d_out, int out_size) {
    const float* x       = (const float*)d_in[0];
    // d_in[1] = masks (unused by the forward pass)
    const float* lpm     = (const float*)d_in[2];
    const float* pm      = (const float*)d_in[3];
    const float* w_first = (const float*)d_in[4];
    const float* w_rest  = (const float*)d_in[5];
    float* out = (float*)d_out;

    precompute_kernel<<<CCH + 1, 512>>>(lpm, pm, w_first, w_rest);
    main_kernel<<<BSEQ, LSEQ>>>(x, out);
}

// round 2
// speedup vs baseline: 1.8092x; 1.8092x over previous
#include <cuda_runtime.h>

#define BSEQ 512
#define LSEQ 512
#define AA   20
#define CCH  8
#define NREST 8
#define POSC 256            // position chunk held in shared at a time

// Precomputed: transposed effective conv map and U = I + V
__device__ float g_WT[LSEQ][CCH];   // WT[p][c] = d out[c] / d h0[p]
__device__ float g_U[AA * AA];      // U[a][i] = (a==i) + V[a][i]

// ---------------------------------------------------------------------------
// Precompute kernel: blocks 0..7 build one column of W_eff via the adjoint of
// the conv+pool pipeline (compile-time unrolled lengths); block 8 builds U.
// ---------------------------------------------------------------------------
template<int LEN2>
__device__ __forceinline__ void adj_layer(const float (*cur)[256],
                                          float (*nxt)[256],
                                          const float* __restrict__ w) {
    for (int idx = threadIdx.x; idx < CCH * LEN2; idx += blockDim.x) {
        const int i = idx / LEN2;          // LEN2 is a power of two -> shift
        const int p = idx % LEN2;
        float acc = 0.f;
        #pragma unroll
        for (int o = 0; o < CCH; ++o) {
            #pragma unroll
            for (int k = 0; k < 3; ++k) {
                const int q = p - k + 1;
                if (q >= 0 && q < LEN2)
                    acc += w[(o * CCH + i) * 3 + k] * 0.5f * cur[o][q >> 1];
            }
        }
        nxt[i][p] = acc;
    }
    __syncthreads();
}

__global__ void precompute_kernel(const float* __restrict__ lpm,
                                  const float* __restrict__ pm,
                                  const float* __restrict__ w_first,
                                  const float* __restrict__ w_rest) {
    const int blk = blockIdx.x;
    const int tid = threadIdx.x;

    if (blk < CCH) {
        __shared__ float bufA[CCH][256];
        __shared__ float bufB[CCH][256];
        __shared__ float wsh[NREST * CCH * CCH * 3];   // 1536 floats

        for (int i = tid; i < NREST * CCH * CCH * 3; i += blockDim.x)
            wsh[i] = w_rest[i];
        if (tid < CCH) bufA[tid][0] = (tid == blk) ? 1.f : 0.f;
        __syncthreads();

        float (*cur)[256] = bufA;
        float (*nxt)[256] = bufB;
        float (*tmp)[256];
        #define STEP(L2, LI) \
            adj_layer<L2>(cur, nxt, wsh + (LI) * CCH * CCH * 3); \
            tmp = cur; cur = nxt; nxt = tmp;
        STEP(2, 7)  STEP(4, 6)  STEP(8, 5)   STEP(16, 4)
        STEP(32, 3) STEP(64, 2) STEP(128, 1) STEP(256, 0)
        #undef STEP

        // Final: adjoint of first conv + its pool (len 256 -> 512).
        for (int p = tid; p < LSEQ; p += blockDim.x) {
            float acc = 0.f;
            #pragma unroll
            for (int o = 0; o < CCH; ++o) {
                #pragma unroll
                for (int k = 0; k < 3; ++k) {
                    const int q = p - k + 1;
                    if (q >= 0 && q < LSEQ)
                        acc += w_first[o * 3 + k] * 0.5f * cur[o][q >> 1];
                }
            }
            g_WT[p][blk] = acc;
        }
    } else {
        // U[a][i] = delta(a,i) + V[a][i]
        for (int idx = tid; idx < AA * AA; idx += blockDim.x) {
            const int a = idx / AA, i = idx % AA;
            float v = (a == i) ? 1.f : 0.f;
            if (i != a && i != AA - 1) {
                const int r = (a < i) ? a : i;
                const int c = (a < i) ? i : a;
                float l = lpm[r * AA + c];
                l = fminf(fmaxf(l, 1e-3f), 1.f);
                v = l * pm[r * AA + c];
            }
            g_U[idx] = v;
        }
    }
}

// ---------------------------------------------------------------------------
// Main kernel: one block per sequence. Dense g = X^T * W via register-tiled
// shared-memory GEMM (no atomics), then out = U^T * g.
//   blockDim = 320 = 10 warps: warp w -> tile (q = w>>1 in 0..4 over a-quads,
//   h = w&1 over c-quads); lanes split p 32-ways.
// ---------------------------------------------------------------------------
__global__ void __launch_bounds__(320)
main_kernel(const float* __restrict__ x, float* __restrict__ out) {
    __shared__ float x_sh[POSC * AA];       // 20 KB, one position chunk
    __shared__ float W_sh[LSEQ][12];        // rows padded 8->12 (bank-safe)
    __shared__ float U_sh[AA * AA];
    __shared__ float g_sh[AA][CCH];

    const int b   = blockIdx.x;
    const int tid = threadIdx.x;
    const int s    = tid & 31;
    const int warp = tid >> 5;              // 0..9
    const int q    = warp >> 1;             // a-quad 0..4
    const int h    = warp & 1;              // c-quad 0..1

    // Stage W (transposed Weff) and U.
    {
        const float4* wg = reinterpret_cast<const float4*>(g_WT);
        for (int i = tid; i < LSEQ * CCH / 4; i += 320) {
            const float4 v = wg[i];
            float* d = &W_sh[i >> 1][(i & 1) << 2];
            d[0] = v.x; d[1] = v.y; d[2] = v.z; d[3] = v.w;
        }
        for (int i = tid; i < AA * AA; i += 320) U_sh[i] = g_U[i];
    }

    float acc[4][4];
    #pragma unroll
    for (int m = 0; m < 4; ++m)
        #pragma unroll
        for (int n = 0; n < 4; ++n) acc[m][n] = 0.f;

    const float4* xg = reinterpret_cast<const float4*>(
        x + (size_t)b * (LSEQ * AA));

    #pragma unroll
    for (int ch = 0; ch < LSEQ / POSC; ++ch) {
        __syncthreads();   // W/U ready (ch=0); x_sh reuse safe (ch=1)
        float4* xs = reinterpret_cast<float4*>(x_sh);
        #pragma unroll
        for (int it = 0; it < POSC * AA / 4 / 320; ++it)
            xs[tid + it * 320] = xg[ch * (POSC * AA / 4) + tid + it * 320];
        __syncthreads();

        #pragma unroll
        for (int j = 0; j < POSC / 32; ++j) {
            const int p = j * 32 + s;       // local position
            const float4 xv = *reinterpret_cast<const float4*>(
                &x_sh[p * AA + q * 4]);
            const float4 wv = *reinterpret_cast<const float4*>(
                &W_sh[ch * POSC + p][h * 4]);
            const float xa[4] = {xv.x, xv.y, xv.z, xv.w};
            const float wa[4] = {wv.x, wv.y, wv.z, wv.w};
            #pragma unroll
            for (int m = 0; m < 4; ++m)
                #pragma unroll
                for (int n = 0; n < 4; ++n)
                    acc[m][n] += xa[m] * wa[n];
        }
    }

    // Cross-lane reduce (sum over p residues held by the 32 lanes).
    #pragma unroll
    for (int m = 0; m < 4; ++m)
        #pragma unroll
        for (int n = 0; n < 4; ++n)
            #pragma unroll
            for (int off = 16; off; off >>= 1)
                acc[m][n] += __shfl_xor_sync(0xffffffffu, acc[m][n], off);

    if (s < 16)
        g_sh[q * 4 + (s >> 2)][h * 4 + (s & 3)] = acc[s >> 2][s & 3];
    __syncthreads();

    // out[b,i,c] = sum_a U[a][i] * g[a][c]
    if (tid < AA * CCH) {
        const int i = tid >> 3;
        const int c = tid & 7;
        float r = 0.f;
        #pragma unroll
        for (int a = 0; a < AA; ++a)
            r += U_sh[a * AA + i] * g_sh[a][c];
        out[(size_t)b * (AA * CCH) + tid] = r;
    }
}

// ---------------------------------------------------------------------------
extern "C" void kernel_launch(void* const* d_in, const int* in_sizes, int n_in,
                              void* d_out, int out_size) {
    const float* x       = (const float*)d_in[0];
    const float* lpm     = (const float*)d_in[2];
    const float* pm      = (const float*)d_in[3];
    const float* w_first = (const float*)d_in[4];
    const float* w_rest  = (const float*)d_in[5];
    float* out = (float*)d_out;

    precompute_kernel<<<CCH + 1, 256>>>(lpm, pm, w_first, w_rest);
    main_kernel<<<BSEQ, 320>>>(x, out);
}